// round 4
// baseline (speedup 1.0000x reference)
#include <cuda_runtime.h>
#include <cstdint>

#define MAXN 100096
#define DD 64

// Scratch (allocation-free rule: __device__ globals)
__device__ float g_bufA[MAXN * DD];
__device__ float g_bufB[MAXN * DD];
__device__ float g_agg [MAXN * DD];

// ---------------------------------------------------------------------------
// Edge scatter: agg[dst] += x[src].  16 threads per edge, float4 per thread,
// 128-bit vector reduction (red.global.add.v4.f32, sm_90+).
// ---------------------------------------------------------------------------
__global__ void __launch_bounds__(256) scatter_kernel(
    const float* __restrict__ x,
    const int*   __restrict__ src,
    const int*   __restrict__ dst,
    float*       __restrict__ agg,
    int nE)
{
    int idx = blockIdx.x * 256 + threadIdx.x;
    int e = idx >> 4;
    if (e >= nE) return;
    int c = idx & 15;

    int s = __ldg(src + e);
    int d = __ldg(dst + e);

    float4 v = __ldg((const float4*)x + (size_t)s * 16 + c);
    float* p = agg + (size_t)d * DD + c * 4;

    asm volatile("red.global.add.v4.f32 [%0], {%1,%2,%3,%4};"
                 :: "l"(p), "f"(v.x), "f"(v.y), "f"(v.z), "f"(v.w)
                 : "memory");
}

// ---------------------------------------------------------------------------
// Fused GIN MLP for one layer:
//   in  = (1+eps[l]) * x + agg
//   h   = relu(in @ W1[l] + b1[l])
//   out = relu(h  @ W2[l] + b2[l])
// One row per thread. W1/W2 in SMEM (broadcast LDS.128). Input row in
// registers (k-loop fully unrolled); h staged in SMEM per-thread column
// (conflict-free, same-thread producer/consumer => no barrier).
// Dynamic SMEM: W1(16K) + W2(16K) + h(32K) + biases = 66048 B.
// ---------------------------------------------------------------------------
#define MLP_SMEM_FLOATS (4096 + 4096 + 8192 + 64 + 64)
#define MLP_SMEM_BYTES  (MLP_SMEM_FLOATS * 4)

__global__ void __launch_bounds__(128) gin_mlp_kernel(
    const float* __restrict__ xin,
    const float* __restrict__ agg,
    const float* __restrict__ W1g,
    const float* __restrict__ b1g,
    const float* __restrict__ W2g,
    const float* __restrict__ b2g,
    const float* __restrict__ eps,
    int l,
    float* __restrict__ xout,
    int n)
{
    extern __shared__ float sm[];
    float* W1s = sm;                 // 4096
    float* W2s = sm + 4096;          // 4096
    float* hs  = sm + 8192;          // 8192  (64 x 128, [k][tid])
    float* b1s = sm + 16384;         // 64
    float* b2s = sm + 16448;         // 64

    const int tid = threadIdx.x;

    // Cooperative weight load
    {
        const float4* g1 = (const float4*)(W1g + (size_t)l * 4096);
        const float4* g2 = (const float4*)(W2g + (size_t)l * 4096);
        float4* s1 = (float4*)W1s;
        float4* s2 = (float4*)W2s;
        for (int i = tid; i < 1024; i += 128) { s1[i] = g1[i]; s2[i] = g2[i]; }
        if (tid < 64) {
            b1s[tid] = b1g[l * 64 + tid];
            b2s[tid] = b2g[l * 64 + tid];
        }
    }
    __syncthreads();

    const int row = blockIdx.x * 128 + tid;
    const bool act = (row < n);
    const float e1 = 1.0f + __ldg(eps + l);

    // Load input row into registers: in = (1+eps)*x + agg
    float in[64];
    if (act) {
        const float4* xr = (const float4*)(xin + (size_t)row * DD);
        const float4* ar = (const float4*)(agg + (size_t)row * DD);
        #pragma unroll
        for (int k = 0; k < 16; k++) {
            float4 a = __ldg(xr + k);
            float4 b = __ldg(ar + k);
            in[4*k+0] = fmaf(e1, a.x, b.x);
            in[4*k+1] = fmaf(e1, a.y, b.y);
            in[4*k+2] = fmaf(e1, a.z, b.z);
            in[4*k+3] = fmaf(e1, a.w, b.w);
        }
    } else {
        #pragma unroll
        for (int k = 0; k < 64; k++) in[k] = 0.0f;
    }

    // GEMM1: h = relu(in @ W1 + b1)  -> staged to SMEM column
    #pragma unroll 1
    for (int jt = 0; jt < 4; jt++) {
        float acc[16];
        #pragma unroll
        for (int j = 0; j < 16; j++) acc[j] = b1s[jt * 16 + j];

        const float4* wb = (const float4*)(W1s + jt * 16);
        #pragma unroll
        for (int k = 0; k < 64; k++) {
            float a = in[k];
            float4 w0 = wb[k * 16 + 0];
            float4 w1 = wb[k * 16 + 1];
            float4 w2 = wb[k * 16 + 2];
            float4 w3 = wb[k * 16 + 3];
            acc[ 0] = fmaf(a, w0.x, acc[ 0]);
            acc[ 1] = fmaf(a, w0.y, acc[ 1]);
            acc[ 2] = fmaf(a, w0.z, acc[ 2]);
            acc[ 3] = fmaf(a, w0.w, acc[ 3]);
            acc[ 4] = fmaf(a, w1.x, acc[ 4]);
            acc[ 5] = fmaf(a, w1.y, acc[ 5]);
            acc[ 6] = fmaf(a, w1.z, acc[ 6]);
            acc[ 7] = fmaf(a, w1.w, acc[ 7]);
            acc[ 8] = fmaf(a, w2.x, acc[ 8]);
            acc[ 9] = fmaf(a, w2.y, acc[ 9]);
            acc[10] = fmaf(a, w2.z, acc[10]);
            acc[11] = fmaf(a, w2.w, acc[11]);
            acc[12] = fmaf(a, w3.x, acc[12]);
            acc[13] = fmaf(a, w3.y, acc[13]);
            acc[14] = fmaf(a, w3.z, acc[14]);
            acc[15] = fmaf(a, w3.w, acc[15]);
        }
        #pragma unroll
        for (int j = 0; j < 16; j++)
            hs[(jt * 16 + j) * 128 + tid] = fmaxf(acc[j], 0.0f);
    }

    // GEMM2: out = relu(h @ W2 + b2)  (h read from own SMEM column)
    #pragma unroll 1
    for (int jt = 0; jt < 4; jt++) {
        float acc[16];
        #pragma unroll
        for (int j = 0; j < 16; j++) acc[j] = b2s[jt * 16 + j];

        const float4* wb = (const float4*)(W2s + jt * 16);
        #pragma unroll 8
        for (int k = 0; k < 64; k++) {
            float a = hs[k * 128 + tid];
            float4 w0 = wb[k * 16 + 0];
            float4 w1 = wb[k * 16 + 1];
            float4 w2 = wb[k * 16 + 2];
            float4 w3 = wb[k * 16 + 3];
            acc[ 0] = fmaf(a, w0.x, acc[ 0]);
            acc[ 1] = fmaf(a, w0.y, acc[ 1]);
            acc[ 2] = fmaf(a, w0.z, acc[ 2]);
            acc[ 3] = fmaf(a, w0.w, acc[ 3]);
            acc[ 4] = fmaf(a, w1.x, acc[ 4]);
            acc[ 5] = fmaf(a, w1.y, acc[ 5]);
            acc[ 6] = fmaf(a, w1.z, acc[ 6]);
            acc[ 7] = fmaf(a, w1.w, acc[ 7]);
            acc[ 8] = fmaf(a, w2.x, acc[ 8]);
            acc[ 9] = fmaf(a, w2.y, acc[ 9]);
            acc[10] = fmaf(a, w2.z, acc[10]);
            acc[11] = fmaf(a, w2.w, acc[11]);
            acc[12] = fmaf(a, w3.x, acc[12]);
            acc[13] = fmaf(a, w3.y, acc[13]);
            acc[14] = fmaf(a, w3.z, acc[14]);
            acc[15] = fmaf(a, w3.w, acc[15]);
        }
        if (act) {
            float4* o = (float4*)(xout + (size_t)row * DD + jt * 16);
            o[0] = make_float4(fmaxf(acc[ 0],0.f), fmaxf(acc[ 1],0.f), fmaxf(acc[ 2],0.f), fmaxf(acc[ 3],0.f));
            o[1] = make_float4(fmaxf(acc[ 4],0.f), fmaxf(acc[ 5],0.f), fmaxf(acc[ 6],0.f), fmaxf(acc[ 7],0.f));
            o[2] = make_float4(fmaxf(acc[ 8],0.f), fmaxf(acc[ 9],0.f), fmaxf(acc[10],0.f), fmaxf(acc[11],0.f));
            o[3] = make_float4(fmaxf(acc[12],0.f), fmaxf(acc[13],0.f), fmaxf(acc[14],0.f), fmaxf(acc[15],0.f));
        }
    }
}

// ---------------------------------------------------------------------------
// Final projection: out = x @ Wf + bf   (no relu)
// ---------------------------------------------------------------------------
__global__ void __launch_bounds__(128) final_kernel(
    const float* __restrict__ xin,
    const float* __restrict__ Wf,
    const float* __restrict__ bf,
    float* __restrict__ out,
    int n)
{
    __shared__ float Ws[4096];
    __shared__ float bs[64];
    const int tid = threadIdx.x;
    {
        const float4* g = (const float4*)Wf;
        float4* s = (float4*)Ws;
        for (int i = tid; i < 1024; i += 128) s[i] = g[i];
        if (tid < 64) bs[tid] = bf[tid];
    }
    __syncthreads();

    const int row = blockIdx.x * 128 + tid;
    const bool act = (row < n);

    float in[64];
    if (act) {
        const float4* xr = (const float4*)(xin + (size_t)row * DD);
        #pragma unroll
        for (int k = 0; k < 16; k++) {
            float4 a = __ldg(xr + k);
            in[4*k+0] = a.x; in[4*k+1] = a.y; in[4*k+2] = a.z; in[4*k+3] = a.w;
        }
    } else {
        #pragma unroll
        for (int k = 0; k < 64; k++) in[k] = 0.0f;
    }

    #pragma unroll 1
    for (int jt = 0; jt < 4; jt++) {
        float acc[16];
        #pragma unroll
        for (int j = 0; j < 16; j++) acc[j] = bs[jt * 16 + j];

        const float4* wb = (const float4*)(Ws + jt * 16);
        #pragma unroll
        for (int k = 0; k < 64; k++) {
            float a = in[k];
            float4 w0 = wb[k * 16 + 0];
            float4 w1 = wb[k * 16 + 1];
            float4 w2 = wb[k * 16 + 2];
            float4 w3 = wb[k * 16 + 3];
            acc[ 0] = fmaf(a, w0.x, acc[ 0]);
            acc[ 1] = fmaf(a, w0.y, acc[ 1]);
            acc[ 2] = fmaf(a, w0.z, acc[ 2]);
            acc[ 3] = fmaf(a, w0.w, acc[ 3]);
            acc[ 4] = fmaf(a, w1.x, acc[ 4]);
            acc[ 5] = fmaf(a, w1.y, acc[ 5]);
            acc[ 6] = fmaf(a, w1.z, acc[ 6]);
            acc[ 7] = fmaf(a, w1.w, acc[ 7]);
            acc[ 8] = fmaf(a, w2.x, acc[ 8]);
            acc[ 9] = fmaf(a, w2.y, acc[ 9]);
            acc[10] = fmaf(a, w2.z, acc[10]);
            acc[11] = fmaf(a, w2.w, acc[11]);
            acc[12] = fmaf(a, w3.x, acc[12]);
            acc[13] = fmaf(a, w3.y, acc[13]);
            acc[14] = fmaf(a, w3.z, acc[14]);
            acc[15] = fmaf(a, w3.w, acc[15]);
        }
        if (act) {
            float4* o = (float4*)(out + (size_t)row * DD + jt * 16);
            o[0] = make_float4(acc[ 0], acc[ 1], acc[ 2], acc[ 3]);
            o[1] = make_float4(acc[ 4], acc[ 5], acc[ 6], acc[ 7]);
            o[2] = make_float4(acc[ 8], acc[ 9], acc[10], acc[11]);
            o[3] = make_float4(acc[12], acc[13], acc[14], acc[15]);
        }
    }
}

// ---------------------------------------------------------------------------
// Launch: 3 x (memset agg; scatter; fused MLP) + final projection.
// All default-stream, graph-capturable, allocation-free.
// ---------------------------------------------------------------------------
extern "C" void kernel_launch(void* const* d_in, const int* in_sizes, int n_in,
                              void* d_out, int out_size)
{
    const float* x   = (const float*)d_in[0];
    const int*   ei  = (const int*)  d_in[1];
    const float* W1  = (const float*)d_in[2];
    const float* b1  = (const float*)d_in[3];
    const float* W2  = (const float*)d_in[4];
    const float* b2  = (const float*)d_in[5];
    const float* eps = (const float*)d_in[6];
    const float* Wf  = (const float*)d_in[7];
    const float* bf  = (const float*)d_in[8];

    const int n = in_sizes[0] / DD;
    const int E = in_sizes[1] / 2;
    const int* src = ei;
    const int* dst = ei + E;

    float *bufA, *bufB, *agg;
    cudaGetSymbolAddress((void**)&bufA, g_bufA);
    cudaGetSymbolAddress((void**)&bufB, g_bufB);
    cudaGetSymbolAddress((void**)&agg,  g_agg);

    cudaFuncSetAttribute(gin_mlp_kernel,
                         cudaFuncAttributeMaxDynamicSharedMemorySize,
                         MLP_SMEM_BYTES);

    const int scatterBlocks = (E * 16 + 255) / 256;
    const int mlpBlocks     = (n + 127) / 128;

    const float* cur = x;
    float*       nxt = bufA;

    for (int l = 0; l < 3; l++) {
        cudaMemsetAsync(agg, 0, (size_t)n * DD * sizeof(float));
        scatter_kernel<<<scatterBlocks, 256>>>(cur, src, dst, agg, E);
        gin_mlp_kernel<<<mlpBlocks, 128, MLP_SMEM_BYTES>>>(
            cur, agg, W1, b1, W2, b2, eps, l, nxt, n);
        cur = nxt;
        nxt = (cur == bufA) ? bufB : bufA;
    }

    final_kernel<<<mlpBlocks, 128>>>(cur, Wf, bf, (float*)d_out, n);
}

// round 5
// speedup vs baseline: 1.5466x; 1.5466x over previous
#include <cuda_runtime.h>
#include <cstdint>

#define MAXN 100096
#define MAXE 1600000
#define DD 64

typedef unsigned long long ull;

// Scratch (allocation-free rule: __device__ globals)
__device__ float g_bufA[MAXN * DD];
__device__ float g_bufB[MAXN * DD];
__device__ float g_hin [MAXN * DD];
__device__ int   g_off [MAXN + 1];
__device__ int   g_cur [MAXN];
__device__ int   g_csr [MAXE];
__device__ int   g_bsum[128];

// ---------------------------------------------------------------------------
// f32x2 packed helpers (sm_100a)
// ---------------------------------------------------------------------------
__device__ __forceinline__ ull pack2(float lo, float hi) {
    ull r; asm("mov.b64 %0,{%1,%2};" : "=l"(r) : "f"(lo), "f"(hi)); return r;
}
__device__ __forceinline__ void unpack2(ull v, float& lo, float& hi) {
    asm("mov.b64 {%0,%1},%2;" : "=f"(lo), "=f"(hi) : "l"(v));
}
__device__ __forceinline__ void ffma2(ull& acc, ull a, ull b) {
    asm("fma.rn.f32x2 %0,%1,%2,%0;" : "+l"(acc) : "l"(a), "l"(b));
}

// ---------------------------------------------------------------------------
// CSR build: histogram -> scan -> fill
// ---------------------------------------------------------------------------
__global__ void hist_kernel(const int* __restrict__ dst, int E,
                            int* __restrict__ deg) {
    int i = blockIdx.x * 256 + threadIdx.x;
    if (i < E) atomicAdd(&deg[__ldg(dst + i)], 1);
}

__global__ void scan1_kernel(const int* __restrict__ deg, int n,
                             int* __restrict__ off, int* __restrict__ bsum) {
    __shared__ int s[1024];
    int i = blockIdx.x * 1024 + threadIdx.x;
    int v = (i < n) ? deg[i] : 0;
    s[threadIdx.x] = v;
    __syncthreads();
    #pragma unroll
    for (int d = 1; d < 1024; d <<= 1) {
        int t = (threadIdx.x >= d) ? s[threadIdx.x - d] : 0;
        __syncthreads();
        s[threadIdx.x] += t;
        __syncthreads();
    }
    if (i < n) off[i] = s[threadIdx.x] - v;          // block-local exclusive
    if (threadIdx.x == 1023) bsum[blockIdx.x] = s[1023];
}

__global__ void scan2_kernel(int* bsum, int nb) {
    if (threadIdx.x == 0 && blockIdx.x == 0) {
        int run = 0;
        for (int b = 0; b < nb; b++) { int t = bsum[b]; bsum[b] = run; run += t; }
    }
}

__global__ void scan3_kernel(int* __restrict__ off, int* __restrict__ cur,
                             const int* __restrict__ bsum, int n, int E) {
    int i = blockIdx.x * 256 + threadIdx.x;
    if (i < n) {
        int v = off[i] + bsum[i >> 10];
        off[i] = v;
        cur[i] = v;
    }
    if (i == 0) off[n] = E;
}

__global__ void fill_kernel(const int* __restrict__ src,
                            const int* __restrict__ dst, int E,
                            int* __restrict__ cur, int* __restrict__ csr) {
    int i = blockIdx.x * 256 + threadIdx.x;
    if (i < E) {
        int d = __ldg(dst + i);
        int p = atomicAdd(&cur[d], 1);
        csr[p] = __ldg(src + i);
    }
}

// ---------------------------------------------------------------------------
// Gather: out[i] = (1+eps)*x[i] + sum_{j in N_in(i)} x[j]
// 16 threads per node, float4 per thread (256B coalesced per neighbor).
// ---------------------------------------------------------------------------
__global__ void __launch_bounds__(256) gather_kernel(
    const float* __restrict__ x,
    const int*   __restrict__ off,
    const int*   __restrict__ csr,
    const float* __restrict__ eps, int l,
    float*       __restrict__ out, int n)
{
    int idx = blockIdx.x * 256 + threadIdx.x;
    int node = idx >> 4;
    if (node >= n) return;
    int c = idx & 15;

    const float4* X = (const float4*)x;
    float e1 = 1.0f + __ldg(eps + l);
    float4 s0 = __ldg(X + (size_t)node * 16 + c);
    float ax = e1 * s0.x, ay = e1 * s0.y, az = e1 * s0.z, aw = e1 * s0.w;

    int beg = __ldg(off + node);
    int end = __ldg(off + node + 1);
    int j = beg;
    for (; j + 3 < end; j += 4) {
        int n0 = __ldg(csr + j);
        int n1 = __ldg(csr + j + 1);
        int n2 = __ldg(csr + j + 2);
        int n3 = __ldg(csr + j + 3);
        float4 a = __ldg(X + (size_t)n0 * 16 + c);
        float4 b = __ldg(X + (size_t)n1 * 16 + c);
        float4 d = __ldg(X + (size_t)n2 * 16 + c);
        float4 e = __ldg(X + (size_t)n3 * 16 + c);
        ax += (a.x + b.x) + (d.x + e.x);
        ay += (a.y + b.y) + (d.y + e.y);
        az += (a.z + b.z) + (d.z + e.z);
        aw += (a.w + b.w) + (d.w + e.w);
    }
    for (; j < end; j++) {
        int n0 = __ldg(csr + j);
        float4 a = __ldg(X + (size_t)n0 * 16 + c);
        ax += a.x; ay += a.y; az += a.z; aw += a.w;
    }
    ((float4*)out)[(size_t)node * 16 + c] = make_float4(ax, ay, az, aw);
}

// ---------------------------------------------------------------------------
// Fused GIN MLP (per layer):
//   h   = relu(hin @ W1[l] + b1[l])
//   out = relu(h   @ W2[l] + b2[l])
// One row/thread, f32x2 packed FMAs, weights in SMEM, h staged in per-thread
// SMEM column (no barrier needed). 256 thr/block, persistent grid (2/SM).
// SMEM floats: b1(64) b2(64) W1(4096) W2(4096) h(16384 = 64x256) = 98816 B
// ---------------------------------------------------------------------------
#define SM_B1 0
#define SM_B2 64
#define SM_W1 128
#define SM_W2 (128 + 4096)
#define SM_H  (128 + 8192)
#define MLP_SMEM_BYTES ((128 + 8192 + 16384) * 4)

__global__ void __launch_bounds__(256, 2) gin_mlp_kernel(
    const float* __restrict__ hin,
    const float* __restrict__ W1g, const float* __restrict__ b1g,
    const float* __restrict__ W2g, const float* __restrict__ b2g,
    int l, float* __restrict__ xout, int n, int nTiles)
{
    extern __shared__ float sm[];
    const int tid = threadIdx.x;
    {
        const float4* g1 = (const float4*)(W1g + (size_t)l * 4096);
        const float4* g2 = (const float4*)(W2g + (size_t)l * 4096);
        float4* s1 = (float4*)(sm + SM_W1);
        float4* s2 = (float4*)(sm + SM_W2);
        for (int i = tid; i < 1024; i += 256) { s1[i] = g1[i]; s2[i] = g2[i]; }
        if (tid < 64)       sm[SM_B1 + tid]        = b1g[l * 64 + tid];
        else if (tid < 128) sm[SM_B2 + (tid - 64)] = b2g[l * 64 + (tid - 64)];
    }
    __syncthreads();
    ull* hs = (ull*)(sm + SM_H);   // [32 pair-rows][256 threads]

    for (int tile = blockIdx.x; tile < nTiles; tile += gridDim.x) {
        int row = tile * 256 + tid;
        bool act = row < n;

        float in[64];
        if (act) {
            const float4* xr = (const float4*)(hin + (size_t)row * DD);
            #pragma unroll
            for (int k = 0; k < 16; k++) {
                float4 a = __ldg(xr + k);
                in[4*k+0] = a.x; in[4*k+1] = a.y; in[4*k+2] = a.z; in[4*k+3] = a.w;
            }
        } else {
            #pragma unroll
            for (int k = 0; k < 64; k++) in[k] = 0.0f;
        }

        // ---- GEMM1: h = relu(in @ W1 + b1) -> SMEM column (packed pairs)
        #pragma unroll 1
        for (int jt = 0; jt < 4; jt++) {
            ull acc[8];
            const ull* bp = (const ull*)(sm + SM_B1 + jt * 16);
            #pragma unroll
            for (int p = 0; p < 8; p++) acc[p] = bp[p];

            #pragma unroll
            for (int k = 0; k < 64; k++) {
                ull a2 = pack2(in[k], in[k]);
                const ulonglong2* w =
                    (const ulonglong2*)(sm + SM_W1 + (k << 6) + (jt << 4));
                ulonglong2 w0 = w[0], w1 = w[1], w2 = w[2], w3 = w[3];
                ffma2(acc[0], a2, w0.x); ffma2(acc[1], a2, w0.y);
                ffma2(acc[2], a2, w1.x); ffma2(acc[3], a2, w1.y);
                ffma2(acc[4], a2, w2.x); ffma2(acc[5], a2, w2.y);
                ffma2(acc[6], a2, w3.x); ffma2(acc[7], a2, w3.y);
            }
            #pragma unroll
            for (int p = 0; p < 8; p++) {
                float lo, hi; unpack2(acc[p], lo, hi);
                hs[(jt * 8 + p) * 256 + tid] = pack2(fmaxf(lo, 0.f), fmaxf(hi, 0.f));
            }
        }

        // ---- GEMM2: out = relu(h @ W2 + b2)
        #pragma unroll 1
        for (int jt = 0; jt < 4; jt++) {
            ull acc[8];
            const ull* bp = (const ull*)(sm + SM_B2 + jt * 16);
            #pragma unroll
            for (int p = 0; p < 8; p++) acc[p] = bp[p];

            #pragma unroll
            for (int k2 = 0; k2 < 32; k2++) {
                float h0, h1; unpack2(hs[k2 * 256 + tid], h0, h1);
                ull a0 = pack2(h0, h0);
                ull a1 = pack2(h1, h1);
                const ulonglong2* wA =
                    (const ulonglong2*)(sm + SM_W2 + ((2*k2)   << 6) + (jt << 4));
                const ulonglong2* wB =
                    (const ulonglong2*)(sm + SM_W2 + ((2*k2+1) << 6) + (jt << 4));
                ulonglong2 u0 = wA[0], u1 = wA[1], u2 = wA[2], u3 = wA[3];
                ffma2(acc[0], a0, u0.x); ffma2(acc[1], a0, u0.y);
                ffma2(acc[2], a0, u1.x); ffma2(acc[3], a0, u1.y);
                ffma2(acc[4], a0, u2.x); ffma2(acc[5], a0, u2.y);
                ffma2(acc[6], a0, u3.x); ffma2(acc[7], a0, u3.y);
                ulonglong2 v0 = wB[0], v1 = wB[1], v2 = wB[2], v3 = wB[3];
                ffma2(acc[0], a1, v0.x); ffma2(acc[1], a1, v0.y);
                ffma2(acc[2], a1, v1.x); ffma2(acc[3], a1, v1.y);
                ffma2(acc[4], a1, v2.x); ffma2(acc[5], a1, v2.y);
                ffma2(acc[6], a1, v3.x); ffma2(acc[7], a1, v3.y);
            }
            if (act) {
                float f[16];
                #pragma unroll
                for (int p = 0; p < 8; p++) unpack2(acc[p], f[2*p], f[2*p+1]);
                float4* o = (float4*)(xout + (size_t)row * DD + jt * 16);
                o[0] = make_float4(fmaxf(f[ 0],0.f), fmaxf(f[ 1],0.f), fmaxf(f[ 2],0.f), fmaxf(f[ 3],0.f));
                o[1] = make_float4(fmaxf(f[ 4],0.f), fmaxf(f[ 5],0.f), fmaxf(f[ 6],0.f), fmaxf(f[ 7],0.f));
                o[2] = make_float4(fmaxf(f[ 8],0.f), fmaxf(f[ 9],0.f), fmaxf(f[10],0.f), fmaxf(f[11],0.f));
                o[3] = make_float4(fmaxf(f[12],0.f), fmaxf(f[13],0.f), fmaxf(f[14],0.f), fmaxf(f[15],0.f));
            }
        }
    }
}

// ---------------------------------------------------------------------------
// Final projection: out = x @ Wf + bf  (no relu), f32x2
// ---------------------------------------------------------------------------
__global__ void __launch_bounds__(256) final_kernel(
    const float* __restrict__ xin,
    const float* __restrict__ Wf,
    const float* __restrict__ bf,
    float* __restrict__ out, int n, int nTiles)
{
    __shared__ float Ws[4096 + 64];
    const int tid = threadIdx.x;
    {
        const float4* g = (const float4*)Wf;
        float4* s = (float4*)Ws;
        for (int i = tid; i < 1024; i += 256) s[i] = g[i];
        if (tid < 64) Ws[4096 + tid] = bf[tid];
    }
    __syncthreads();

    for (int tile = blockIdx.x; tile < nTiles; tile += gridDim.x) {
        int row = tile * 256 + tid;
        bool act = row < n;

        float in[64];
        if (act) {
            const float4* xr = (const float4*)(xin + (size_t)row * DD);
            #pragma unroll
            for (int k = 0; k < 16; k++) {
                float4 a = __ldg(xr + k);
                in[4*k+0] = a.x; in[4*k+1] = a.y; in[4*k+2] = a.z; in[4*k+3] = a.w;
            }
        } else {
            #pragma unroll
            for (int k = 0; k < 64; k++) in[k] = 0.0f;
        }

        #pragma unroll 1
        for (int jt = 0; jt < 4; jt++) {
            ull acc[8];
            const ull* bp = (const ull*)(Ws + 4096 + jt * 16);
            #pragma unroll
            for (int p = 0; p < 8; p++) acc[p] = bp[p];

            #pragma unroll
            for (int k = 0; k < 64; k++) {
                ull a2 = pack2(in[k], in[k]);
                const ulonglong2* w =
                    (const ulonglong2*)(Ws + (k << 6) + (jt << 4));
                ulonglong2 w0 = w[0], w1 = w[1], w2 = w[2], w3 = w[3];
                ffma2(acc[0], a2, w0.x); ffma2(acc[1], a2, w0.y);
                ffma2(acc[2], a2, w1.x); ffma2(acc[3], a2, w1.y);
                ffma2(acc[4], a2, w2.x); ffma2(acc[5], a2, w2.y);
                ffma2(acc[6], a2, w3.x); ffma2(acc[7], a2, w3.y);
            }
            if (act) {
                float f[16];
                #pragma unroll
                for (int p = 0; p < 8; p++) unpack2(acc[p], f[2*p], f[2*p+1]);
                float4* o = (float4*)(out + (size_t)row * DD + jt * 16);
                o[0] = make_float4(f[ 0], f[ 1], f[ 2], f[ 3]);
                o[1] = make_float4(f[ 4], f[ 5], f[ 6], f[ 7]);
                o[2] = make_float4(f[ 8], f[ 9], f[10], f[11]);
                o[3] = make_float4(f[12], f[13], f[14], f[15]);
            }
        }
    }
}

// ---------------------------------------------------------------------------
// Launch: CSR build once, then 3 x (gather; fused MLP) + final projection.
// All default-stream, graph-capturable, allocation-free.
// ---------------------------------------------------------------------------
extern "C" void kernel_launch(void* const* d_in, const int* in_sizes, int n_in,
                              void* d_out, int out_size)
{
    const float* x   = (const float*)d_in[0];
    const int*   ei  = (const int*)  d_in[1];
    const float* W1  = (const float*)d_in[2];
    const float* b1  = (const float*)d_in[3];
    const float* W2  = (const float*)d_in[4];
    const float* b2  = (const float*)d_in[5];
    const float* eps = (const float*)d_in[6];
    const float* Wf  = (const float*)d_in[7];
    const float* bf  = (const float*)d_in[8];

    const int n = in_sizes[0] / DD;
    const int E = in_sizes[1] / 2;
    const int* src = ei;
    const int* dst = ei + E;

    float *bufA, *bufB, *hin;
    int *off, *cur, *csr, *bsum;
    cudaGetSymbolAddress((void**)&bufA, g_bufA);
    cudaGetSymbolAddress((void**)&bufB, g_bufB);
    cudaGetSymbolAddress((void**)&hin,  g_hin);
    cudaGetSymbolAddress((void**)&off,  g_off);
    cudaGetSymbolAddress((void**)&cur,  g_cur);
    cudaGetSymbolAddress((void**)&csr,  g_csr);
    cudaGetSymbolAddress((void**)&bsum, g_bsum);

    cudaFuncSetAttribute(gin_mlp_kernel,
                         cudaFuncAttributeMaxDynamicSharedMemorySize,
                         MLP_SMEM_BYTES);

    // ---- CSR build (per call; deterministic up to fp-benign edge ordering)
    cudaMemsetAsync(cur, 0, (size_t)n * sizeof(int));
    hist_kernel<<<(E + 255) / 256, 256>>>(dst, E, cur);
    const int nb = (n + 1023) / 1024;
    scan1_kernel<<<nb, 1024>>>(cur, n, off, bsum);
    scan2_kernel<<<1, 32>>>(bsum, nb);
    scan3_kernel<<<(n + 255) / 256, 256>>>(off, cur, bsum, n, E);
    fill_kernel<<<(E + 255) / 256, 256>>>(src, dst, E, cur, csr);

    // ---- Layers
    const int gatherBlocks = (n * 16 + 255) / 256;
    const int mlpTiles = (n + 255) / 256;
    int mlpGrid = 296;                       // 2 blocks x 148 SMs
    if (mlpGrid > mlpTiles) mlpGrid = mlpTiles;

    const float* curx = x;
    float*       nxt  = bufA;
    for (int l = 0; l < 3; l++) {
        gather_kernel<<<gatherBlocks, 256>>>(curx, off, csr, eps, l, hin, n);
        gin_mlp_kernel<<<mlpGrid, 256, MLP_SMEM_BYTES>>>(
            hin, W1, b1, W2, b2, l, nxt, n, mlpTiles);
        curx = nxt;
        nxt = (curx == bufA) ? bufB : bufA;
    }

    final_kernel<<<mlpGrid, 256>>>(curx, Wf, bf, (float*)d_out, n, mlpTiles);
}